// round 9
// baseline (speedup 1.0000x reference)
#include <cuda_runtime.h>
#include <math.h>
#include <stdint.h>

#define BATCH    16384
#define MAZE_LEN 3844
#define NWARPS   4096          // each warp does rows w, w+4096, w+8192, w+12288

// 120 needed columns per row (3721 double-counted), all reciprocal-summed:
//   -log(clip(prod, e^-90)) == min(log(S - 127), 90)
// (S includes 8 dummy 1.0-reciprocals from inactive mid lanes per row.)
//
// Warm-replay theory: 87 MB of touched 128B lines fits L2 (126 MB) but full
// evict_last (frac 1.0, R4) overflows the protected ways -> LRU churn.
// Fractional 0.5 pins a stable ~44 MB subset across graph replays; the rest
// streams. Steady-state DRAM bytes should roughly halve.

__device__ __forceinline__ float fast_rcp(float x) {
    float r;
    asm("rcp.approx.ftz.f32 %0, %1;" : "=f"(r) : "f"(x));
    return r;
}

// Scalar non-coherent load with an L2 cache policy attached.
__device__ __forceinline__ float ldg_pol(const float* p, uint64_t pol) {
    float v;
    asm("ld.global.nc.L2::cache_hint.f32 %0, [%1], %2;"
        : "=f"(v) : "l"(p), "l"(pol));
    return v;
}

// Fold 4 reciprocals into one MUFU.RCP.
__device__ __forceinline__ float fold4(float h, float t, float m0, float m1) {
    const float a   = h * t;
    const float b   = m0 * m1;
    const float num = (h + t) * b + (m0 + m1) * a;
    return num * fast_rcp(a * b);
}

__global__ __launch_bounds__(256)
void fuzzy_chain_kernel(const float* __restrict__ maze, float* __restrict__ out)
{
    const int warp_local  = threadIdx.x >> 5;                 // 0..7
    const int warp_global = blockIdx.x * 8 + warp_local;
    const int lane        = threadIdx.x & 31;

    // Fractional evict_last policy: pin ~half the lines in protected ways.
    uint64_t pol;
    asm("createpolicy.fractional.L2::evict_last.b64 %0, 0.5;" : "=l"(pol));

    // ---- per-lane scalar indices (shared by all 4 rows) ------------------
    int h_i = 4 * lane + 1;
    if (lane == 0) h_i = 1;
    if (lane == 1) h_i = 6;

    int t_i = 3717 + 4 * lane;
    if (lane == 29) t_i = 3721;                   // duplicate 3721
    if (lane == 30) t_i = 3839;
    if (lane == 31) t_i = 3841;

    const int k     = lane >> 1;
    const int comp  = lane & 1;
    const int p1    = 16 + k;
    const bool act1 = (p1 < 28);
    const int m0_i  = 124 * k + 245 + 4 * comp;
    const int m1_i  = 124 * (act1 ? p1 : 27) + 245 + 4 * comp;

    const float* __restrict__ r0 = maze + (size_t)warp_global * MAZE_LEN;
    const float* __restrict__ r1 = r0 + (size_t)NWARPS * MAZE_LEN;
    const float* __restrict__ r2 = r1 + (size_t)NWARPS * MAZE_LEN;
    const float* __restrict__ r3 = r2 + (size_t)NWARPS * MAZE_LEN;

    // ---- front-batch all 16 scalar loads (MLP=16), evict_last 0.5 --------
    const float h0 = ldg_pol(r0 + h_i, pol), t0 = ldg_pol(r0 + t_i, pol);
    const float a0 = ldg_pol(r0 + m0_i, pol), b0l = ldg_pol(r0 + m1_i, pol);
    const float h1 = ldg_pol(r1 + h_i, pol), t1 = ldg_pol(r1 + t_i, pol);
    const float a1 = ldg_pol(r1 + m0_i, pol), b1l = ldg_pol(r1 + m1_i, pol);
    const float h2 = ldg_pol(r2 + h_i, pol), t2 = ldg_pol(r2 + t_i, pol);
    const float a2 = ldg_pol(r2 + m0_i, pol), b2l = ldg_pol(r2 + m1_i, pol);
    const float h3 = ldg_pol(r3 + h_i, pol), t3 = ldg_pol(r3 + t_i, pol);
    const float a3 = ldg_pol(r3 + m0_i, pol), b3l = ldg_pol(r3 + m1_i, pol);

    const float b0 = act1 ? b0l : 1.0f;           // dummy -> rcp(1)=1, in constant
    const float b1 = act1 ? b1l : 1.0f;
    const float b2 = act1 ? b2l : 1.0f;
    const float b3 = act1 ? b3l : 1.0f;

    float s0 = fold4(h0, t0, a0, b0);
    float s1 = fold4(h1, t1, a1, b1);
    float s2 = fold4(h2, t2, a2, b2);
    float s3 = fold4(h3, t3, a3, b3);

    // ---- warp reduction of all 4 rows' S ---------------------------------
    #pragma unroll
    for (int off = 16; off > 0; off >>= 1) {
        s0 += __shfl_xor_sync(0xffffffffu, s0, off);
        s1 += __shfl_xor_sync(0xffffffffu, s1, off);
        s2 += __shfl_xor_sync(0xffffffffu, s2, off);
        s3 += __shfl_xor_sync(0xffffffffu, s3, off);
    }

    __shared__ float warp_vals[8];
    if (lane == 0) {
        // x==0 -> inf -> fminf -> 90; two zeros -> NaN -> fminf -> 90 (matches clip).
        const float v0 = fminf(logf(s0 - 127.0f), 90.0f);
        const float v1 = fminf(logf(s1 - 127.0f), 90.0f);
        const float v2 = fminf(logf(s2 - 127.0f), 90.0f);
        const float v3 = fminf(logf(s3 - 127.0f), 90.0f);
        warp_vals[warp_local] = (v0 + v1) + (v2 + v3);
    }
    __syncthreads();

    if (threadIdx.x == 0) {
        float t = 0.0f;
        #pragma unroll
        for (int i = 0; i < 8; i++) t += warp_vals[i];
        atomicAdd(out, t * (1.0f / (float)BATCH));   // exact power-of-two scale
    }
}

extern "C" void kernel_launch(void* const* d_in, const int* in_sizes, int n_in,
                              void* d_out, int out_size)
{
    const float* maze = (const float*)d_in[0];
    float*       out  = (float*)d_out;

    cudaMemsetAsync(out, 0, sizeof(float), 0);

    const int blocks = NWARPS / 8;                  // 512 CTAs, 256 threads each
    fuzzy_chain_kernel<<<blocks, 256>>>(maze, out);
}